// round 2
// baseline (speedup 1.0000x reference)
#include <cuda_runtime.h>
#include <math.h>

typedef unsigned long long ull;

#define B_  32
#define N_  196
#define C_  32
#define K_  64
#define P_  100

// ---------------- scratch (device globals, no allocation) ----------------
__device__ float g_DS[B_ * N_ * C_];     // diag of Sigma_in, [b][n][c]   (~0.8MB)
__device__ float g_S [B_ * N_ * N_];     // per-batch spatial gram        (~4.9M floats)
__device__ float g_G [B_ * P_ * P_];     // patch gram                    (320K floats)
__device__ float g_DV[B_ * P_ * K_];     // diag_vals                     (204800 floats)
__device__ float g_SP[K_];               // softplus(w_sigma)

// ---------------- f32x2 helpers ----------------
__device__ __forceinline__ ull pack2dup(float x) {
    ull r; asm("mov.b64 %0, {%1, %1};" : "=l"(r) : "f"(x)); return r;
}
__device__ __forceinline__ void unpack2(ull v, float& lo, float& hi) {
    asm("mov.b64 {%0, %1}, %2;" : "=f"(lo), "=f"(hi) : "l"(v));
}
__device__ __forceinline__ void fma2(ull& acc, ull a, ull b) {
    asm("fma.rn.f32x2 %0, %1, %2, %0;" : "+l"(acc) : "l"(a), "l"(b));
}
__device__ __forceinline__ void stcs4(float4* p, float4 v) {
    asm volatile("st.global.cs.v4.f32 [%0], {%1, %2, %3, %4};"
                 :: "l"(p), "f"(v.x), "f"(v.y), "f"(v.z), "f"(v.w) : "memory");
}

// ---------------- K0: diag gather + softplus ----------------
__global__ void k0_prep(const float* __restrict__ Sigma_in,
                        const float* __restrict__ w_sigma) {
    int i = blockIdx.x * 256 + threadIdx.x;           // exactly B*N*C threads
    if (i < B_ * N_ * C_) {
        int c = i & 31;
        int n = (i >> 5) % N_;
        int b = i / (N_ * C_);
        g_DS[i] = Sigma_in[((b * N_ + n) * N_ + n) * C_ + c];
    }
    if (i < K_) g_SP[i] = log1pf(expf(w_sigma[i]));
}

// ---------------- K1: S[b][n1][n2] = sum_c mu[b][n1][c]*mu[b][n2][c] ----------------
// grid (13, 32), 256 threads; smem mu tile, rows padded to 9 float4 (bank rotate)
__global__ void k1_sgram(const float* __restrict__ mu_in) {
    __shared__ float4 musm[N_ * 9];
    int b   = blockIdx.y;
    int bt  = blockIdx.x;            // n1 tile of 16
    int tid = threadIdx.x;
    const float4* mu4 = (const float4*)mu_in + b * (N_ * C_ / 4);
    for (int idx = tid; idx < N_ * 8; idx += 256)
        musm[(idx >> 3) * 9 + (idx & 7)] = mu4[idx];
    __syncthreads();

    int i1 = tid >> 4, jn2 = tid & 15;
    int n1 = bt * 16 + i1;
    if (n1 < N_) {
        float4 a[8];
#pragma unroll
        for (int j = 0; j < 8; j++) a[j] = musm[n1 * 9 + j];
        for (int n2 = jn2; n2 < N_; n2 += 16) {
            float acc = 0.f;
#pragma unroll
            for (int j = 0; j < 8; j++) {
                float4 bv = musm[n2 * 9 + j];
                acc += a[j].x * bv.x + a[j].y * bv.y + a[j].z * bv.z + a[j].w * bv.w;
            }
            g_S[(b * N_ + n1) * N_ + n2] = acc;
        }
    }
}

// ---------------- K2: G[b][p][q] = sum over 25 taps of S ----------------
__global__ void k2_g() {
    int i = blockIdx.x * 256 + threadIdx.x;
    if (i >= B_ * P_ * P_) return;
    int q = i % 100; int t = i / 100; int p = t % 100; int b = t / 100;
    int pi = p / 10, pj = p % 10, qi = q / 10, qj = q % 10;
    const float* Sb = g_S + b * N_ * N_;
    float s = 0.f;
#pragma unroll
    for (int ki = 0; ki < 5; ki++) {
        int r1 = (pi + ki) * 14 + pj;
        int r2 = (qi + ki) * 14 + qj;
#pragma unroll
        for (int kj = 0; kj < 5; kj++)
            s += Sb[(r1 + kj) * N_ + (r2 + kj)];
    }
    g_G[i] = s;
}

// ---------------- K3: dual conv (mu_out and v1) + trace + diag_vals ----------------
// grid (5, 32): (p-tile of 20, batch). 160 threads = 4 m-splits x 8 kgroups x 5 pgroups.
// Thread tile: 4 p x 4 k-pairs (8 k), f32x2 FMA, both matrices at once.
__global__ __launch_bounds__(160) void k3_conv(const float* __restrict__ mu_in,
                                               const float* __restrict__ w_mu,
                                               float* __restrict__ mu_out) {
    __shared__ __align__(16) float Rmu[2688];    // 6 rows x 14 x 32
    __shared__ __align__(16) float Rds[2688];
    __shared__ __align__(16) float wsm_mu[2048]; // 32 c x 64 k (one tap)
    __shared__ __align__(16) float wsm_w2[2048];
    __shared__ float resmu[1280];                // 20 p x 64 k
    __shared__ float resv1[1280];
    __shared__ float trsm[20];

    int pt = blockIdx.x;                // 0..4  (p-tile: rows pt*2, pt*2+1)
    int b  = blockIdx.y;
    int tid = threadIdx.x;
    int ms = tid & 3;                   // m-split over channels
    int kg = (tid >> 2) & 7;            // k group
    int pg = tid >> 5;                  // warp == p group (0..4)
    int k0 = kg * 8;

    {   // region load (contiguous 2688 floats) + zero result buffers
        const float4* mu4 = (const float4*)mu_in + (b * 1568 + pt * 224);
        const float4* ds4 = (const float4*)g_DS  + (b * 1568 + pt * 224);
        float4* Rm4 = (float4*)Rmu; float4* Rd4 = (float4*)Rds;
        for (int idx = tid; idx < 672; idx += 160) { Rm4[idx] = mu4[idx]; Rd4[idx] = ds4[idx]; }
        for (int idx = tid; idx < 1280; idx += 160) { resmu[idx] = 0.f; resv1[idx] = 0.f; }
    }

    int aofs[4];
#pragma unroll
    for (int pp = 0; pp < 4; pp++) {
        int pl = pg * 4 + pp;                        // 0..19
        aofs[pp] = ((pl / 10) * 14 + (pl % 10)) * 32;
    }

    ull accmu[4][4], accv1[4][4];
#pragma unroll
    for (int a = 0; a < 4; a++)
#pragma unroll
        for (int j = 0; j < 4; j++) { accmu[a][j] = 0ULL; accv1[a][j] = 0ULL; }

    for (int tap = 0; tap < 25; tap++) {
        __syncthreads();
        {   // stage this tap's weights (and their squares)
            const float4* wg = (const float4*)w_mu + tap * 512;
            float4* wm4 = (float4*)wsm_mu; float4* w24 = (float4*)wsm_w2;
            for (int idx = tid; idx < 512; idx += 160) {
                float4 w = wg[idx];
                wm4[idx] = w;
                float4 w2; w2.x = w.x*w.x; w2.y = w.y*w.y; w2.z = w.z*w.z; w2.w = w.w*w.w;
                w24[idx] = w2;
            }
        }
        __syncthreads();
        int ki = tap / 5, kj = tap - ki * 5;
        int tapofs = (ki * 14 + kj) * 32;
#pragma unroll
        for (int c8 = 0; c8 < 8; c8++) {
            int c = ms * 8 + c8;
            int ao = tapofs + c;
            ull wmu2[4], w22[4];
            const ull* wpm = (const ull*)(wsm_mu + c * 64 + k0);
            const ull* wp2 = (const ull*)(wsm_w2 + c * 64 + k0);
#pragma unroll
            for (int j = 0; j < 4; j++) { wmu2[j] = wpm[j]; w22[j] = wp2[j]; }
#pragma unroll
            for (int pp = 0; pp < 4; pp++) {
                ull a2 = pack2dup(Rmu[aofs[pp] + ao]);
                ull d2 = pack2dup(Rds[aofs[pp] + ao]);
#pragma unroll
                for (int j = 0; j < 4; j++) {
                    fma2(accmu[pp][j], a2, wmu2[j]);
                    fma2(accv1[pp][j], d2, w22[j]);
                }
            }
        }
    }
    __syncthreads();

    // reduce the 4 m-splits into smem
#pragma unroll
    for (int pp = 0; pp < 4; pp++) {
        int pl = pg * 4 + pp;
#pragma unroll
        for (int j = 0; j < 4; j++) {
            float lo, hi;
            unpack2(accmu[pp][j], lo, hi);
            atomicAdd(&resmu[pl * 64 + k0 + 2 * j],     lo);
            atomicAdd(&resmu[pl * 64 + k0 + 2 * j + 1], hi);
            unpack2(accv1[pp][j], lo, hi);
            atomicAdd(&resv1[pl * 64 + k0 + 2 * j],     lo);
            atomicAdd(&resv1[pl * 64 + k0 + 2 * j + 1], hi);
        }
    }

    // trace: 8 lanes per p, shfl-reduce
    {
        int p_t = tid >> 3, lane8 = tid & 7;          // p_t 0..19
        int ao = ((p_t / 10) * 14 + (p_t % 10)) * 32;
        float s = 0.f;
#pragma unroll
        for (int tap = 0; tap < 25; tap++) {
            int ki = tap / 5, kj = tap - ki * 5;
            int to = ao + (ki * 14 + kj) * 32;
            for (int cc = lane8; cc < 32; cc += 8) s += Rds[to + cc];
        }
        s += __shfl_down_sync(0xffffffffu, s, 4, 8);
        s += __shfl_down_sync(0xffffffffu, s, 2, 8);
        s += __shfl_down_sync(0xffffffffu, s, 1, 8);
        if (lane8 == 0) trsm[p_t] = s;
    }
    __syncthreads();

    // write mu_out and diag_vals
    for (int o = tid; o < 1280; o += 160) {
        int pl = o >> 6, k = o & 63;
        int pglob = pt * 20 + pl;
        int gi = (b * 100 + pglob) * 64 + k;
        mu_out[gi] = resmu[o];
        g_DV[gi]  = resv1[o] + g_SP[k] * trsm[pl];
    }
}

// ---------------- K4: Sigma_out writer (streaming, float4 + st.cs) ----------------
__global__ void k4_sigma(float* __restrict__ out) {
    int i = blockIdx.x * 256 + threadIdx.x;    // exactly 5,120,000 threads (float4 units)
    int k4 = i & 15;
    int t  = i >> 4;
    int q  = t % 100; int t2 = t / 100; int p = t2 % 100; int b = t2 / 100;

    float g = __ldg(&g_G[(b * 100 + p) * 100 + q]);
    const float4* SP4 = (const float4*)g_SP;
    float4 sp = SP4[k4];
    float4 v;
    v.x = sp.x * g; v.y = sp.y * g; v.z = sp.z * g; v.w = sp.w * g;
    if (p == q) {
        const float4* DV4 = (const float4*)g_DV;
        float4 dv = DV4[(b * 100 + p) * 16 + k4];
        v.x += dv.x; v.y += dv.y; v.z += dv.z; v.w += dv.w;
    }
    if (!isfinite(v.x)) v.x = 0.f;
    if (!isfinite(v.y)) v.y = 0.f;
    if (!isfinite(v.z)) v.z = 0.f;
    if (!isfinite(v.w)) v.w = 0.f;
    if ((q >> 2) == k4) {                       // q == k (only possible for q < 64)
        int r = q & 3;
        if      (r == 0) v.x = fabsf(v.x);
        else if (r == 1) v.y = fabsf(v.y);
        else if (r == 2) v.z = fabsf(v.z);
        else             v.w = fabsf(v.w);
    }
    stcs4(((float4*)out) + 51200 + i, v);       // Sigma_out starts after mu_out (204800 floats)
}

// ---------------- launch ----------------
extern "C" void kernel_launch(void* const* d_in, const int* in_sizes, int n_in,
                              void* d_out, int out_size) {
    const float* mu_in    = (const float*)d_in[0];
    const float* Sigma_in = (const float*)d_in[1];
    const float* w_mu     = (const float*)d_in[2];
    const float* w_sigma  = (const float*)d_in[3];
    float* out = (float*)d_out;

    k0_prep <<<784, 256>>>(Sigma_in, w_sigma);          // 784*256 == 32*196*32
    k1_sgram<<<dim3(13, 32), 256>>>(mu_in);
    k2_g    <<<1250, 256>>>();
    k3_conv <<<dim3(5, 32), 160>>>(mu_in, w_mu, out);
    k4_sigma<<<20000, 256>>>(out);                      // 20000*256*16B == Sigma_out bytes
}

// round 3
// speedup vs baseline: 1.8278x; 1.8278x over previous
#include <cuda_runtime.h>
#include <math.h>

typedef unsigned long long ull;

#define B_  32
#define N_  196
#define C_  32
#define K_  64
#define P_  100

// ---------------- scratch (device globals, no allocation) ----------------
__device__ float g_DS[B_ * N_ * C_];     // diag of Sigma_in, [b][n][c]
__device__ float g_S [B_ * N_ * N_];     // per-batch spatial gram
__device__ float g_G [B_ * P_ * P_];     // patch gram
__device__ float g_DV[B_ * P_ * K_];     // diag_vals
__device__ float g_SP[K_];               // softplus(w_sigma)
__device__ float g_W2[25 * C_ * K_];     // w_mu^2, same layout as w_mu

// ---------------- f32x2 helpers ----------------
__device__ __forceinline__ ull pack2dup(float x) {
    ull r; asm("mov.b64 %0, {%1, %1};" : "=l"(r) : "f"(x)); return r;
}
__device__ __forceinline__ void unpack2(ull v, float& lo, float& hi) {
    asm("mov.b64 {%0, %1}, %2;" : "=f"(lo), "=f"(hi) : "l"(v));
}
__device__ __forceinline__ void fma2(ull& acc, ull a, ull b) {
    asm("fma.rn.f32x2 %0, %1, %2, %0;" : "+l"(acc) : "l"(a), "l"(b));
}
__device__ __forceinline__ void stcs4(float4* p, float4 v) {
    asm volatile("st.global.cs.v4.f32 [%0], {%1, %2, %3, %4};"
                 :: "l"(p), "f"(v.x), "f"(v.y), "f"(v.z), "f"(v.w) : "memory");
}

// ---------------- K0: diag gather + softplus + w^2 ----------------
__global__ void k0_prep(const float* __restrict__ Sigma_in,
                        const float* __restrict__ w_sigma,
                        const float* __restrict__ w_mu) {
    int i = blockIdx.x * 256 + threadIdx.x;           // 784*256 = 200704 threads
    if (i < B_ * N_ * C_) {
        int c = i & 31;
        int n = (i >> 5) % N_;
        int b = i / (N_ * C_);
        g_DS[i] = Sigma_in[((b * N_ + n) * N_ + n) * C_ + c];
    }
    if (i < 25 * C_ * K_) {
        float w = w_mu[i];
        g_W2[i] = w * w;
    }
    if (i < K_) g_SP[i] = log1pf(expf(w_sigma[i]));
}

// ---------------- K1: S[b][n1][n2] = sum_c mu[b][n1][c]*mu[b][n2][c] ----------------
__global__ void k1_sgram(const float* __restrict__ mu_in) {
    __shared__ float4 musm[N_ * 9];
    int b   = blockIdx.y;
    int bt  = blockIdx.x;            // n1 tile of 16
    int tid = threadIdx.x;
    const float4* mu4 = (const float4*)mu_in + b * (N_ * C_ / 4);
    for (int idx = tid; idx < N_ * 8; idx += 256)
        musm[(idx >> 3) * 9 + (idx & 7)] = mu4[idx];
    __syncthreads();

    int i1 = tid >> 4, jn2 = tid & 15;
    int n1 = bt * 16 + i1;
    if (n1 < N_) {
        float4 a[8];
#pragma unroll
        for (int j = 0; j < 8; j++) a[j] = musm[n1 * 9 + j];
        for (int n2 = jn2; n2 < N_; n2 += 16) {
            float acc = 0.f;
#pragma unroll
            for (int j = 0; j < 8; j++) {
                float4 bv = musm[n2 * 9 + j];
                acc += a[j].x * bv.x + a[j].y * bv.y + a[j].z * bv.z + a[j].w * bv.w;
            }
            g_S[(b * N_ + n1) * N_ + n2] = acc;
        }
    }
}

// ---------------- K2: G[b][p][q] = sum over 25 taps of S ----------------
__global__ void k2_g() {
    int i = blockIdx.x * 256 + threadIdx.x;
    if (i >= B_ * P_ * P_) return;
    int q = i % 100; int t = i / 100; int p = t % 100; int b = t / 100;
    int pi = p / 10, pj = p % 10, qi = q / 10, qj = q % 10;
    const float* Sb = g_S + b * N_ * N_;
    float s = 0.f;
#pragma unroll
    for (int ki = 0; ki < 5; ki++) {
        int r1 = (pi + ki) * 14 + pj;
        int r2 = (qi + ki) * 14 + qj;
#pragma unroll
        for (int kj = 0; kj < 5; kj++)
            s += Sb[(r1 + kj) * N_ + (r2 + kj)];
    }
    g_G[i] = s;
}

// ---------------- K3: dual conv (mu_out / v1) + trace + diag_vals ----------------
// grid (5, 32): (p-tile of 20, batch). 256 threads = 8 warps.
//   mset = wid>>2 : 0 -> mu conv (weights w), 1 -> v1 conv (weights w^2)
//   wp   = wid&3  : 5-p group (p_local = wp*5 .. wp*5+4)
//   lane          : k-pair (k = 2*lane, 2*lane+1), one f32x2 acc per p.
// No atomics; each lane writes its own float2 outputs.
__global__ __launch_bounds__(256) void k3_conv(const float* __restrict__ mu_in,
                                               const float* __restrict__ w_mu,
                                               float* __restrict__ mu_out) {
    __shared__ __align__(16) float Rmu[2688];    // 6 rows x 14 x 32
    __shared__ __align__(16) float Rds[2688];
    __shared__ __align__(16) float wsm [2048];   // 32 c x 64 k (one tap)
    __shared__ __align__(16) float wsm2[2048];
    __shared__ float trsm[20];

    int pt   = blockIdx.x;               // 0..4
    int b    = blockIdx.y;
    int tid  = threadIdx.x;
    int wid  = tid >> 5;
    int lane = tid & 31;
    int mset = wid >> 2;                 // 0 = mu, 1 = v1
    int wp   = wid & 3;                  // p-group

    {   // region load (contiguous 2688 floats each)
        const float4* mu4 = (const float4*)mu_in + (b * 1568 + pt * 224);
        const float4* ds4 = (const float4*)g_DS  + (b * 1568 + pt * 224);
        float4* Rm4 = (float4*)Rmu; float4* Rd4 = (float4*)Rds;
        for (int idx = tid; idx < 672; idx += 256) { Rm4[idx] = mu4[idx]; Rd4[idx] = ds4[idx]; }
    }

    int aofs[5];
#pragma unroll
    for (int pp = 0; pp < 5; pp++) {
        int pl = wp * 5 + pp;                        // 0..19
        aofs[pp] = ((pl / 10) * 14 + (pl % 10)) * 32;
    }

    const float* A = mset ? Rds  : Rmu;
    const float* W = mset ? wsm2 : wsm;

    ull acc[5];
#pragma unroll
    for (int pp = 0; pp < 5; pp++) acc[pp] = 0ULL;

    for (int tap = 0; tap < 25; tap++) {
        __syncthreads();
        {   // stage this tap's weights (copy, squares precomputed)
            const float4* wg  = (const float4*)w_mu + tap * 512;
            const float4* w2g = (const float4*)g_W2 + tap * 512;
            float4* wm4 = (float4*)wsm; float4* w24 = (float4*)wsm2;
#pragma unroll
            for (int r = 0; r < 2; r++) {
                int idx = tid + r * 256;
                wm4[idx] = wg[idx];
                w24[idx] = w2g[idx];
            }
        }
        __syncthreads();
        int ki = tap / 5, kj = tap - ki * 5;
        int tofs = (ki * 14 + kj) * 32;
        int base[5];
#pragma unroll
        for (int pp = 0; pp < 5; pp++) base[pp] = aofs[pp] + tofs;

#pragma unroll
        for (int c = 0; c < 32; c += 2) {
            ull w0 = ((const ull*)(W + c * 64))[lane];
            ull w1 = ((const ull*)(W + c * 64 + 64))[lane];
#pragma unroll
            for (int pp = 0; pp < 5; pp++) {
                float2 a = *(const float2*)(A + base[pp] + c);
                fma2(acc[pp], pack2dup(a.x), w0);
                fma2(acc[pp], pack2dup(a.y), w1);
            }
        }
    }
    __syncthreads();

    // trace over Rds patches: 160 threads (warps 0..4), 8 lanes per p
    if (tid < 160) {
        int p_t = tid >> 3, lane8 = tid & 7;
        int ao = ((p_t / 10) * 14 + (p_t % 10)) * 32;
        float s = 0.f;
#pragma unroll
        for (int tap = 0; tap < 25; tap++) {
            int ki = tap / 5, kj = tap - ki * 5;
            int to = ao + (ki * 14 + kj) * 32;
            for (int cc = lane8; cc < 32; cc += 8) s += Rds[to + cc];
        }
        s += __shfl_down_sync(0xffffffffu, s, 4, 8);
        s += __shfl_down_sync(0xffffffffu, s, 2, 8);
        s += __shfl_down_sync(0xffffffffu, s, 1, 8);
        if (lane8 == 0) trsm[p_t] = s;
    }
    __syncthreads();

    // direct stores (coalesced float2 per lane)
    if (mset == 0) {
#pragma unroll
        for (int pp = 0; pp < 5; pp++) {
            int pglob = pt * 20 + wp * 5 + pp;
            float lo, hi; unpack2(acc[pp], lo, hi);
            float2* dst = (float2*)(mu_out + (b * 100 + pglob) * 64) + lane;
            *dst = make_float2(lo, hi);
        }
    } else {
        float splo = g_SP[2 * lane], sphi = g_SP[2 * lane + 1];
#pragma unroll
        for (int pp = 0; pp < 5; pp++) {
            int pl = wp * 5 + pp;
            int pglob = pt * 20 + pl;
            float lo, hi; unpack2(acc[pp], lo, hi);
            float tr = trsm[pl];
            lo += splo * tr; hi += sphi * tr;
            float2* dst = (float2*)(g_DV + (b * 100 + pglob) * 64) + lane;
            *dst = make_float2(lo, hi);
        }
    }
}

// ---------------- K4: Sigma_out writer (streaming, float4 + st.cs) ----------------
__global__ void k4_sigma(float* __restrict__ out) {
    int i = blockIdx.x * 256 + threadIdx.x;    // 5,120,000 float4 units
    int k4 = i & 15;
    int t  = i >> 4;
    int q  = t % 100; int t2 = t / 100; int p = t2 % 100; int b = t2 / 100;

    float g = __ldg(&g_G[(b * 100 + p) * 100 + q]);
    const float4* SP4 = (const float4*)g_SP;
    float4 sp = SP4[k4];
    float4 v;
    v.x = sp.x * g; v.y = sp.y * g; v.z = sp.z * g; v.w = sp.w * g;
    if (p == q) {
        const float4* DV4 = (const float4*)g_DV;
        float4 dv = DV4[(b * 100 + p) * 16 + k4];
        v.x += dv.x; v.y += dv.y; v.z += dv.z; v.w += dv.w;
    }
    if (!isfinite(v.x)) v.x = 0.f;
    if (!isfinite(v.y)) v.y = 0.f;
    if (!isfinite(v.z)) v.z = 0.f;
    if (!isfinite(v.w)) v.w = 0.f;
    if ((q >> 2) == k4) {                       // q == k (only possible for q < 64)
        int r = q & 3;
        if      (r == 0) v.x = fabsf(v.x);
        else if (r == 1) v.y = fabsf(v.y);
        else if (r == 2) v.z = fabsf(v.z);
        else             v.w = fabsf(v.w);
    }
    stcs4(((float4*)out) + 51200 + i, v);       // Sigma_out after mu_out (204800 floats)
}

// ---------------- launch ----------------
extern "C" void kernel_launch(void* const* d_in, const int* in_sizes, int n_in,
                              void* d_out, int out_size) {
    const float* mu_in    = (const float*)d_in[0];
    const float* Sigma_in = (const float*)d_in[1];
    const float* w_mu     = (const float*)d_in[2];
    const float* w_sigma  = (const float*)d_in[3];
    float* out = (float*)d_out;

    k0_prep <<<784, 256>>>(Sigma_in, w_sigma, w_mu);
    k1_sgram<<<dim3(13, 32), 256>>>(mu_in);
    k2_g    <<<1250, 256>>>();
    k3_conv <<<dim3(5, 32), 256>>>(mu_in, w_mu, out);
    k4_sigma<<<20000, 256>>>(out);
}